// round 1
// baseline (speedup 1.0000x reference)
#include <cuda_runtime.h>
#include <cuda_bf16.h>
#include <math.h>

// Problem constants
#define BATCH 2
#define SEQ   2048
#define DMODEL 1024
#define NHEADS 16
#define DK    64
#define MTOT  (BATCH*SEQ)          // 4096
#define QKV_N (3*DMODEL)           // 3072

// Scratch (device globals — no allocation allowed)
__device__ float g_qkv[(size_t)MTOT * QKV_N];   // [b,s, 3*d]  (e = which*1024 + h*64 + dk)
__device__ float g_att[(size_t)MTOT * DMODEL];  // [b,s, h*64+dk]

// ---------------------------------------------------------------------------
// GEMM: C[M,N] = A[M,K] * B[N,K]^T   (both row-major; "NT" / torch-Linear form)
// 128x128 block tile, BK=16, 256 threads, 8x8 per thread (4+4 split vectors)
// M % 128 == 0, N % 128 == 0, K % 16 == 0 assumed (holds for all 3 shapes).
// ---------------------------------------------------------------------------
#define BM 128
#define BN 128
#define BK 16

__global__ void __launch_bounds__(256, 2) gemm_nt(
    const float* __restrict__ A, const float* __restrict__ B,
    float* __restrict__ C, int M, int N, int K)
{
    __shared__ float As[BK][BM];
    __shared__ float Bs[BK][BN];

    const int tid = threadIdx.x;
    const int tx = tid & 15;        // 0..15 -> N direction
    const int ty = tid >> 4;        // 0..15 -> M direction
    const int mBase = blockIdx.y * BM;
    const int nBase = blockIdx.x * BN;

    float acc[8][8];
#pragma unroll
    for (int i = 0; i < 8; i++)
#pragma unroll
        for (int j = 0; j < 8; j++) acc[i][j] = 0.f;

    for (int k0 = 0; k0 < K; k0 += BK) {
        __syncthreads();
        // Load A,B tiles: 128 rows x 16 cols each = 512 float4; 2 per thread per matrix.
#pragma unroll
        for (int it = 0; it < 2; it++) {
            int lin = (tid + it * 256) * 4;      // 0..2044
            int row = lin >> 4;                  // 0..127
            int kk  = lin & 15;                  // 0,4,8,12
            float4 va = *(const float4*)(A + (size_t)(mBase + row) * K + k0 + kk);
            As[kk+0][row] = va.x; As[kk+1][row] = va.y;
            As[kk+2][row] = va.z; As[kk+3][row] = va.w;
            float4 vb = *(const float4*)(B + (size_t)(nBase + row) * K + k0 + kk);
            Bs[kk+0][row] = vb.x; Bs[kk+1][row] = vb.y;
            Bs[kk+2][row] = vb.z; Bs[kk+3][row] = vb.w;
        }
        __syncthreads();

#pragma unroll
        for (int kk = 0; kk < BK; kk++) {
            float4 a0 = *(const float4*)&As[kk][ty * 4];
            float4 a1 = *(const float4*)&As[kk][64 + ty * 4];
            float4 b0 = *(const float4*)&Bs[kk][tx * 4];
            float4 b1 = *(const float4*)&Bs[kk][64 + tx * 4];
            float ar[8] = {a0.x, a0.y, a0.z, a0.w, a1.x, a1.y, a1.z, a1.w};
            float br[8] = {b0.x, b0.y, b0.z, b0.w, b1.x, b1.y, b1.z, b1.w};
#pragma unroll
            for (int i = 0; i < 8; i++)
#pragma unroll
                for (int j = 0; j < 8; j++)
                    acc[i][j] = fmaf(ar[i], br[j], acc[i][j]);
        }
    }

    // Write back
#pragma unroll
    for (int i = 0; i < 8; i++) {
        int row = mBase + ((i < 4) ? (ty * 4 + i) : (64 + ty * 4 + i - 4));
        float* crow = C + (size_t)row * N + nBase;
        *(float4*)(crow + tx * 4)      = make_float4(acc[i][0], acc[i][1], acc[i][2], acc[i][3]);
        *(float4*)(crow + 64 + tx * 4) = make_float4(acc[i][4], acc[i][5], acc[i][6], acc[i][7]);
    }
}

// ---------------------------------------------------------------------------
// Causal flash attention, fp32, online softmax.
// Grid: (SEQ/128 q-tiles, NHEADS, BATCH).  Block: 128 threads, 1 query/thread.
// K/V streamed through shared memory in tiles of 64 keys.
// ---------------------------------------------------------------------------
#define QB 128
#define KB 64

__global__ void __launch_bounds__(QB) attn_kernel()
{
    const int b  = blockIdx.z;
    const int h  = blockIdx.y;
    const int qt = blockIdx.x;
    const int tid = threadIdx.x;
    const int qi = qt * QB + tid;                 // global query index in [0,SEQ)

    __shared__ float Ks[KB][DK];
    __shared__ float Vs[KB][DK];

    float q[DK], acc[DK];
    const float scale = 0.125f;                   // 1/sqrt(64)

    const float* qrow = g_qkv + ((size_t)(b * SEQ + qi)) * QKV_N + h * DK;
#pragma unroll
    for (int d = 0; d < DK; d += 4) {
        float4 v = *(const float4*)(qrow + d);
        q[d] = v.x * scale; q[d+1] = v.y * scale; q[d+2] = v.z * scale; q[d+3] = v.w * scale;
        acc[d] = 0.f; acc[d+1] = 0.f; acc[d+2] = 0.f; acc[d+3] = 0.f;
    }
    float m = -1e30f, l = 0.f;

    const int kend = qt * QB + QB;                // last key needed +1 for this block
    for (int k0 = 0; k0 < kend; k0 += KB) {
        __syncthreads();
        // cooperative load of K/V tile: 64 rows x 16 float4 = 1024 float4 -> 8/thread
        for (int i = tid; i < KB * (DK / 4); i += QB) {
            int row = i >> 4;
            int c4  = (i & 15) * 4;
            size_t base = ((size_t)(b * SEQ + k0 + row)) * QKV_N + h * DK + c4;
            float4 vk = *(const float4*)(g_qkv + base + DMODEL);       // K slab
            Ks[row][c4] = vk.x; Ks[row][c4+1] = vk.y; Ks[row][c4+2] = vk.z; Ks[row][c4+3] = vk.w;
            float4 vv = *(const float4*)(g_qkv + base + 2 * DMODEL);   // V slab
            Vs[row][c4] = vv.x; Vs[row][c4+1] = vv.y; Vs[row][c4+2] = vv.z; Vs[row][c4+3] = vv.w;
        }
        __syncthreads();

        int jmax = qi - k0 + 1;
        if (jmax > KB) jmax = KB;
        for (int j = 0; j < jmax; j++) {
            float s = 0.f;
#pragma unroll
            for (int d = 0; d < DK; d++) s = fmaf(q[d], Ks[j][d], s);
            float m_new = fmaxf(m, s);
            if (m_new > m) {
                float corr = __expf(m - m_new);
                l *= corr;
#pragma unroll
                for (int d = 0; d < DK; d++) acc[d] *= corr;
                m = m_new;
            }
            float p = __expf(s - m_new);
            l += p;
#pragma unroll
            for (int d = 0; d < DK; d++) acc[d] = fmaf(p, Vs[j][d], acc[d]);
        }
    }

    const float inv = 1.f / l;
    float* orow = g_att + ((size_t)(b * SEQ + qi)) * DMODEL + h * DK;
#pragma unroll
    for (int d = 0; d < DK; d += 4) {
        *(float4*)(orow + d) = make_float4(acc[d] * inv, acc[d+1] * inv,
                                           acc[d+2] * inv, acc[d+3] * inv);
    }
}

// ---------------------------------------------------------------------------
// kernel_launch
// ---------------------------------------------------------------------------
extern "C" void kernel_launch(void* const* d_in, const int* in_sizes, int n_in,
                              void* d_out, int out_size)
{
    const float* x     = (const float*)d_in[0];   // [2, 2048, 1024]
    const float* W_qkv = (const float*)d_in[1];   // [3072, 1024]
    const float* W_out = (const float*)d_in[2];   // [1024, 1024]
    float* out = (float*)d_out;                   // [2, 2048, 1024]

    float* qkv_ptr = nullptr;
    float* att_ptr = nullptr;
    cudaGetSymbolAddress((void**)&qkv_ptr, g_qkv);
    cudaGetSymbolAddress((void**)&att_ptr, g_att);

    // 1) QKV projection: [4096,1024] x [3072,1024]^T -> [4096,3072]
    {
        dim3 grid(QKV_N / BN, MTOT / BM);
        gemm_nt<<<grid, 256>>>(x, W_qkv, qkv_ptr, MTOT, QKV_N, DMODEL);
    }
    // 2) causal flash attention -> g_att [4096,1024]
    {
        dim3 grid(SEQ / QB, NHEADS, BATCH);
        attn_kernel<<<grid, QB>>>();
    }
    // 3) output projection: [4096,1024] x [1024,1024]^T -> d_out
    {
        dim3 grid(DMODEL / BN, MTOT / BM);
        gemm_nt<<<grid, 256>>>(att_ptr, W_out, out, MTOT, DMODEL, DMODEL);
    }
}

// round 2
// speedup vs baseline: 1.2951x; 1.2951x over previous
#include <cuda_runtime.h>
#include <cuda_bf16.h>
#include <math.h>

// Problem constants
#define BATCH 2
#define SEQ   2048
#define DMODEL 1024
#define NHEADS 16
#define DK    64
#define MTOT  (BATCH*SEQ)          // 4096
#define QKV_N (3*DMODEL)           // 3072

// Scratch (device globals — no allocation allowed)
__device__ float g_qkv[(size_t)MTOT * QKV_N];   // [b,s, 3*d]
__device__ float g_att[(size_t)MTOT * DMODEL];  // [b,s, h*64+dk]

// ---------------------------------------------------------------------------
// GEMM: C[M,N] = A[M,K] * B[N,K]^T, 128x128 tile, BK=16, 256 thr, 8x8/thread.
// Double-buffered smem + register prefetch of next K-slice.
// ---------------------------------------------------------------------------
#define BM 128
#define BN 128
#define BK 16

__global__ void __launch_bounds__(256, 2) gemm_nt(
    const float* __restrict__ A, const float* __restrict__ B,
    float* __restrict__ C, int M, int N, int K)
{
    __shared__ float As[2][BK][BM];   // 16KB
    __shared__ float Bs[2][BK][BN];   // 16KB

    const int tid = threadIdx.x;
    const int tx = tid & 15;
    const int ty = tid >> 4;
    const int mBase = blockIdx.y * BM;
    const int nBase = blockIdx.x * BN;

    // load mapping: each thread loads rows (row, row+64) at k-offset kk
    const int row = tid >> 2;            // 0..63
    const int kk  = (tid & 3) * 4;       // 0,4,8,12
    const float* Ap0 = A + (size_t)(mBase + row) * K + kk;
    const float* Ap1 = A + (size_t)(mBase + row + 64) * K + kk;
    const float* Bp0 = B + (size_t)(nBase + row) * K + kk;
    const float* Bp1 = B + (size_t)(nBase + row + 64) * K + kk;

    float acc[8][8];
#pragma unroll
    for (int i = 0; i < 8; i++)
#pragma unroll
        for (int j = 0; j < 8; j++) acc[i][j] = 0.f;

    // prologue: tile 0 -> buffer 0
    {
        float4 a0 = *(const float4*)(Ap0);
        float4 a1 = *(const float4*)(Ap1);
        float4 b0 = *(const float4*)(Bp0);
        float4 b1 = *(const float4*)(Bp1);
        As[0][kk+0][row] = a0.x; As[0][kk+1][row] = a0.y; As[0][kk+2][row] = a0.z; As[0][kk+3][row] = a0.w;
        As[0][kk+0][row+64] = a1.x; As[0][kk+1][row+64] = a1.y; As[0][kk+2][row+64] = a1.z; As[0][kk+3][row+64] = a1.w;
        Bs[0][kk+0][row] = b0.x; Bs[0][kk+1][row] = b0.y; Bs[0][kk+2][row] = b0.z; Bs[0][kk+3][row] = b0.w;
        Bs[0][kk+0][row+64] = b1.x; Bs[0][kk+1][row+64] = b1.y; Bs[0][kk+2][row+64] = b1.z; Bs[0][kk+3][row+64] = b1.w;
    }
    __syncthreads();

    int buf = 0;
    for (int k0 = BK; k0 <= K; k0 += BK) {
        float4 pa0, pa1, pb0, pb1;
        const bool more = (k0 < K);
        if (more) {
            pa0 = *(const float4*)(Ap0 + k0);
            pa1 = *(const float4*)(Ap1 + k0);
            pb0 = *(const float4*)(Bp0 + k0);
            pb1 = *(const float4*)(Bp1 + k0);
        }

        // compute on current buffer
#pragma unroll
        for (int k = 0; k < BK; k++) {
            float4 a0 = *(const float4*)&As[buf][k][ty * 4];
            float4 a1 = *(const float4*)&As[buf][k][64 + ty * 4];
            float4 b0 = *(const float4*)&Bs[buf][k][tx * 4];
            float4 b1 = *(const float4*)&Bs[buf][k][64 + tx * 4];
            float ar[8] = {a0.x, a0.y, a0.z, a0.w, a1.x, a1.y, a1.z, a1.w};
            float br[8] = {b0.x, b0.y, b0.z, b0.w, b1.x, b1.y, b1.z, b1.w};
#pragma unroll
            for (int i = 0; i < 8; i++)
#pragma unroll
                for (int j = 0; j < 8; j++)
                    acc[i][j] = fmaf(ar[i], br[j], acc[i][j]);
        }

        if (more) {
            int nb = buf ^ 1;
            As[nb][kk+0][row] = pa0.x; As[nb][kk+1][row] = pa0.y; As[nb][kk+2][row] = pa0.z; As[nb][kk+3][row] = pa0.w;
            As[nb][kk+0][row+64] = pa1.x; As[nb][kk+1][row+64] = pa1.y; As[nb][kk+2][row+64] = pa1.z; As[nb][kk+3][row+64] = pa1.w;
            Bs[nb][kk+0][row] = pb0.x; Bs[nb][kk+1][row] = pb0.y; Bs[nb][kk+2][row] = pb0.z; Bs[nb][kk+3][row] = pb0.w;
            Bs[nb][kk+0][row+64] = pb1.x; Bs[nb][kk+1][row+64] = pb1.y; Bs[nb][kk+2][row+64] = pb1.z; Bs[nb][kk+3][row+64] = pb1.w;
            __syncthreads();
            buf = nb;
        }
    }

#pragma unroll
    for (int i = 0; i < 8; i++) {
        int r = mBase + ((i < 4) ? (ty * 4 + i) : (64 + ty * 4 + i - 4));
        float* crow = C + (size_t)r * N + nBase;
        *(float4*)(crow + tx * 4)      = make_float4(acc[i][0], acc[i][1], acc[i][2], acc[i][3]);
        *(float4*)(crow + 64 + tx * 4) = make_float4(acc[i][4], acc[i][5], acc[i][6], acc[i][7]);
    }
}

// ---------------------------------------------------------------------------
// Register-tiled causal flash attention.
// Block = 128 threads, handles 64 queries of one (b,h). Tiles of 64 keys.
// Thread (tx in [0,16), ty in [0,8)) owns 8 queries x (4 keys | 4 dk cols).
// K tile is XOR-swizzled (column-group ^ (row>>2)) for conflict-free LDS.128.
// ---------------------------------------------------------------------------
#define AQT 64
#define AKT 64

__global__ void __launch_bounds__(128, 3) attn_kernel(
    const float* __restrict__ qkv, float* __restrict__ att)
{
    extern __shared__ float sm[];
    float* Qs = sm;           // [64][64]
    float* Ks = sm + 4096;    // [64][64] swizzled
    float* Vs = sm + 8192;    // [64][64]
    float* Ss = sm + 12288;   // [64][64]

    const int b  = blockIdx.z;
    const int h  = blockIdx.y;
    const int qt = (int)(gridDim.x - 1 - blockIdx.x);   // heavy tiles first
    const int tid = threadIdx.x;
    const int tx = tid & 15;
    const int ty = tid >> 4;
    const int q0 = qt * AQT;
    const float scale = 0.125f;   // 1/sqrt(64)

    // Load Q tile, pre-scaled
    for (int e = tid; e < 64 * 16; e += 128) {
        int r = e >> 4, c4 = (e & 15) << 2;
        float4 v = *(const float4*)(qkv + ((size_t)(b * SEQ + q0 + r)) * QKV_N + h * DK + c4);
        v.x *= scale; v.y *= scale; v.z *= scale; v.w *= scale;
        *(float4*)&Qs[r * 64 + c4] = v;
    }

    float O[8][4];
    float m[8], l[8];
#pragma unroll
    for (int i = 0; i < 8; i++) {
        m[i] = -1e30f; l[i] = 0.f;
        O[i][0] = O[i][1] = O[i][2] = O[i][3] = 0.f;
    }
    __syncthreads();

    for (int kt = 0; kt <= qt; kt++) {
        const int kbase = kt * AKT;

        // Load K (swizzled) and V tiles
        for (int e = tid; e < 64 * 16; e += 128) {
            int r = e >> 4, c4 = e & 15;
            size_t gbase = ((size_t)(b * SEQ + kbase + r)) * QKV_N + h * DK + (c4 << 2);
            float4 kv = *(const float4*)(qkv + gbase + DMODEL);
            *(float4*)&Ks[r * 64 + ((c4 ^ (r >> 2)) << 2)] = kv;
            float4 vv = *(const float4*)(qkv + gbase + 2 * DMODEL);
            *(float4*)&Vs[r * 64 + (c4 << 2)] = vv;
        }
        __syncthreads();

        // Phase 1: S = Q K^T (8x4 per thread)
        float s[8][4];
#pragma unroll
        for (int i = 0; i < 8; i++) { s[i][0]=0.f; s[i][1]=0.f; s[i][2]=0.f; s[i][3]=0.f; }

#pragma unroll 4
        for (int kk4 = 0; kk4 < 16; kk4++) {
            const int kcol = ((kk4 ^ tx) << 2);   // (row>>2)==tx for rows 4tx..4tx+3
            float4 kv0 = *(const float4*)&Ks[(tx * 4 + 0) * 64 + kcol];
            float4 kv1 = *(const float4*)&Ks[(tx * 4 + 1) * 64 + kcol];
            float4 kv2 = *(const float4*)&Ks[(tx * 4 + 2) * 64 + kcol];
            float4 kv3 = *(const float4*)&Ks[(tx * 4 + 3) * 64 + kcol];
#pragma unroll
            for (int i = 0; i < 8; i++) {
                float4 qv = *(const float4*)&Qs[(ty * 8 + i) * 64 + (kk4 << 2)];
                s[i][0] = fmaf(qv.x, kv0.x, fmaf(qv.y, kv0.y, fmaf(qv.z, kv0.z, fmaf(qv.w, kv0.w, s[i][0]))));
                s[i][1] = fmaf(qv.x, kv1.x, fmaf(qv.y, kv1.y, fmaf(qv.z, kv1.z, fmaf(qv.w, kv1.w, s[i][1]))));
                s[i][2] = fmaf(qv.x, kv2.x, fmaf(qv.y, kv2.y, fmaf(qv.z, kv2.z, fmaf(qv.w, kv2.w, s[i][2]))));
                s[i][3] = fmaf(qv.x, kv3.x, fmaf(qv.y, kv3.y, fmaf(qv.z, kv3.z, fmaf(qv.w, kv3.w, s[i][3]))));
            }
        }

        // Causal mask on diagonal tile (kbase == q0)
        if (kt == qt) {
#pragma unroll
            for (int i = 0; i < 8; i++) {
                int qq = ty * 8 + i;
#pragma unroll
                for (int j = 0; j < 4; j++)
                    if (tx * 4 + j > qq) s[i][j] = -1e30f;
            }
        }

        // Online softmax update + write P into Ss
#pragma unroll
        for (int i = 0; i < 8; i++) {
            float mx = fmaxf(fmaxf(s[i][0], s[i][1]), fmaxf(s[i][2], s[i][3]));
            mx = fmaxf(mx, __shfl_xor_sync(0xffffffffu, mx, 1));
            mx = fmaxf(mx, __shfl_xor_sync(0xffffffffu, mx, 2));
            mx = fmaxf(mx, __shfl_xor_sync(0xffffffffu, mx, 4));
            mx = fmaxf(mx, __shfl_xor_sync(0xffffffffu, mx, 8));
            float mn = fmaxf(m[i], mx);
            float p0 = __expf(s[i][0] - mn);
            float p1 = __expf(s[i][1] - mn);
            float p2 = __expf(s[i][2] - mn);
            float p3 = __expf(s[i][3] - mn);
            float sum = (p0 + p1) + (p2 + p3);
            sum += __shfl_xor_sync(0xffffffffu, sum, 1);
            sum += __shfl_xor_sync(0xffffffffu, sum, 2);
            sum += __shfl_xor_sync(0xffffffffu, sum, 4);
            sum += __shfl_xor_sync(0xffffffffu, sum, 8);
            float corr = __expf(m[i] - mn);
            m[i] = mn;
            l[i] = l[i] * corr + sum;
            O[i][0] *= corr; O[i][1] *= corr; O[i][2] *= corr; O[i][3] *= corr;
            *(float4*)&Ss[(ty * 8 + i) * 64 + tx * 4] = make_float4(p0, p1, p2, p3);
        }
        __syncthreads();

        // Phase 3: O += P V  (j unrolled by 4, vector loads of P)
#pragma unroll 4
        for (int j4 = 0; j4 < 16; j4++) {
            float4 v0 = *(const float4*)&Vs[(j4 * 4 + 0) * 64 + tx * 4];
            float4 v1 = *(const float4*)&Vs[(j4 * 4 + 1) * 64 + tx * 4];
            float4 v2 = *(const float4*)&Vs[(j4 * 4 + 2) * 64 + tx * 4];
            float4 v3 = *(const float4*)&Vs[(j4 * 4 + 3) * 64 + tx * 4];
#pragma unroll
            for (int i = 0; i < 8; i++) {
                float4 p = *(const float4*)&Ss[(ty * 8 + i) * 64 + j4 * 4];
                O[i][0] = fmaf(p.x, v0.x, fmaf(p.y, v1.x, fmaf(p.z, v2.x, fmaf(p.w, v3.x, O[i][0]))));
                O[i][1] = fmaf(p.x, v0.y, fmaf(p.y, v1.y, fmaf(p.z, v2.y, fmaf(p.w, v3.y, O[i][1]))));
                O[i][2] = fmaf(p.x, v0.z, fmaf(p.y, v1.z, fmaf(p.z, v2.z, fmaf(p.w, v3.z, O[i][2]))));
                O[i][3] = fmaf(p.x, v0.w, fmaf(p.y, v1.w, fmaf(p.z, v2.w, fmaf(p.w, v3.w, O[i][3]))));
            }
        }
        __syncthreads();   // before next tile overwrites Ks/Vs/Ss
    }

    // Epilogue: normalize and write
#pragma unroll
    for (int i = 0; i < 8; i++) {
        float inv = 1.f / l[i];
        float* orow = att + ((size_t)(b * SEQ + q0 + ty * 8 + i)) * DMODEL + h * DK;
        *(float4*)(orow + tx * 4) = make_float4(O[i][0] * inv, O[i][1] * inv,
                                                O[i][2] * inv, O[i][3] * inv);
    }
}

// ---------------------------------------------------------------------------
// kernel_launch
// ---------------------------------------------------------------------------
extern "C" void kernel_launch(void* const* d_in, const int* in_sizes, int n_in,
                              void* d_out, int out_size)
{
    const float* x     = (const float*)d_in[0];   // [2, 2048, 1024]
    const float* W_qkv = (const float*)d_in[1];   // [3072, 1024]
    const float* W_out = (const float*)d_in[2];   // [1024, 1024]
    float* out = (float*)d_out;                   // [2, 2048, 1024]

    float* qkv_ptr = nullptr;
    float* att_ptr = nullptr;
    cudaGetSymbolAddress((void**)&qkv_ptr, g_qkv);
    cudaGetSymbolAddress((void**)&att_ptr, g_att);

    // attention needs 64KB dynamic smem
    cudaFuncSetAttribute(attn_kernel, cudaFuncAttributeMaxDynamicSharedMemorySize, 65536);

    // 1) QKV projection: [4096,1024] x [3072,1024]^T -> [4096,3072]
    {
        dim3 grid(QKV_N / BN, MTOT / BM);
        gemm_nt<<<grid, 256>>>(x, W_qkv, qkv_ptr, MTOT, QKV_N, DMODEL);
    }
    // 2) causal flash attention -> g_att [4096,1024]
    {
        dim3 grid(SEQ / AQT, NHEADS, BATCH);
        attn_kernel<<<grid, 128, 65536>>>(qkv_ptr, att_ptr);
    }
    // 3) output projection: [4096,1024] x [1024,1024]^T -> d_out
    {
        dim3 grid(DMODEL / BN, MTOT / BM);
        gemm_nt<<<grid, 256>>>(att_ptr, W_out, out, MTOT, DMODEL, DMODEL);
    }
}

// round 3
// speedup vs baseline: 1.9935x; 1.5392x over previous
#include <cuda_runtime.h>
#include <cuda_bf16.h>
#include <math.h>
#include <stdint.h>

// Problem constants
#define BATCH 2
#define SEQ   2048
#define DMODEL 1024
#define NHEADS 16
#define DK    64
#define MTOT  (BATCH*SEQ)          // 4096
#define QKV_N (3*DMODEL)           // 3072
#define KEXT  (3*DMODEL)           // 3072 extended-K for bf16 split

// Scratch (device globals — no allocation allowed)
__device__ float g_qkv[(size_t)MTOT * QKV_N];        // f32 qkv
__device__ float g_att[(size_t)MTOT * DMODEL];       // f32 attention out
__device__ __nv_bfloat16 g_xe   [(size_t)MTOT  * KEXT];   // x extended   (A: hi,lo,hi)
__device__ __nv_bfloat16 g_wqkve[(size_t)QKV_N * KEXT];   // W_qkv ext    (B: hi,hi,lo)
__device__ __nv_bfloat16 g_wute [(size_t)DMODEL* KEXT];   // W_out ext    (B)
__device__ __nv_bfloat16 g_atte [(size_t)MTOT  * KEXT];   // att extended (A)

// ---------------------------------------------------------------------------
// Split-conversion kernels: f32 [R,K] -> bf16 [R,3K]
//  A mode: [k]=hi  [K+k]=lo  [2K+k]=hi
//  B mode: [k]=hi  [K+k]=hi  [2K+k]=lo
// ---------------------------------------------------------------------------
template<int ISA>
__global__ void conv_split(const float* __restrict__ in, __nv_bfloat16* __restrict__ out,
                           int K, size_t total /* R*K */)
{
    size_t idx = ((size_t)blockIdx.x * blockDim.x + threadIdx.x) * 4;
    if (idx >= total) return;
    int r = (int)(idx / K);
    int k = (int)(idx % K);
    float4 v = *(const float4*)(in + idx);
    __nv_bfloat162 hi01, hi23, lo01, lo23;
    float a0 = v.x, a1 = v.y, a2 = v.z, a3 = v.w;
    __nv_bfloat16 h0 = __float2bfloat16_rn(a0);
    __nv_bfloat16 h1 = __float2bfloat16_rn(a1);
    __nv_bfloat16 h2 = __float2bfloat16_rn(a2);
    __nv_bfloat16 h3 = __float2bfloat16_rn(a3);
    hi01 = __nv_bfloat162(h0, h1); hi23 = __nv_bfloat162(h2, h3);
    lo01 = __nv_bfloat162(__float2bfloat16_rn(a0 - __bfloat162float(h0)),
                          __float2bfloat16_rn(a1 - __bfloat162float(h1)));
    lo23 = __nv_bfloat162(__float2bfloat16_rn(a2 - __bfloat162float(h2)),
                          __float2bfloat16_rn(a3 - __bfloat162float(h3)));
    __nv_bfloat16* o = out + (size_t)r * (3 * K) + k;
    *(__nv_bfloat162*)(o + 0) = hi01;  *(__nv_bfloat162*)(o + 2) = hi23;
    if (ISA) {
        *(__nv_bfloat162*)(o + K + 0)     = lo01; *(__nv_bfloat162*)(o + K + 2)     = lo23;
        *(__nv_bfloat162*)(o + 2 * K + 0) = hi01; *(__nv_bfloat162*)(o + 2 * K + 2) = hi23;
    } else {
        *(__nv_bfloat162*)(o + K + 0)     = hi01; *(__nv_bfloat162*)(o + K + 2)     = hi23;
        *(__nv_bfloat162*)(o + 2 * K + 0) = lo01; *(__nv_bfloat162*)(o + 2 * K + 2) = lo23;
    }
}

// ---------------------------------------------------------------------------
// bf16 tensor-core GEMM: C[M,N] f32 = A[M,KEXT] * B[N,KEXT]^T
// 128x128 block, BK=32, 256 thr (8 warps, 2x4), warp tile 64x32.
// mma.sync.m16n8k16.bf16, ldmatrix, cp.async double buffer.
// Smem swizzle: 16B segment s at row r -> s ^ ((r>>1)&3)  (conflict-free).
// ---------------------------------------------------------------------------
#define TILE_ELEMS (128*32)

__device__ __forceinline__ void ldm_x4(uint32_t& r0, uint32_t& r1, uint32_t& r2, uint32_t& r3,
                                       uint32_t addr)
{
    asm volatile("ldmatrix.sync.aligned.m8n8.x4.shared.b16 {%0,%1,%2,%3}, [%4];"
                 : "=r"(r0), "=r"(r1), "=r"(r2), "=r"(r3) : "r"(addr));
}

__device__ __forceinline__ void mma16816(float* d, const uint32_t* a, const uint32_t* b)
{
    asm volatile(
        "mma.sync.aligned.m16n8k16.row.col.f32.bf16.bf16.f32 "
        "{%0,%1,%2,%3}, {%4,%5,%6,%7}, {%8,%9}, {%0,%1,%2,%3};"
        : "+f"(d[0]), "+f"(d[1]), "+f"(d[2]), "+f"(d[3])
        : "r"(a[0]), "r"(a[1]), "r"(a[2]), "r"(a[3]), "r"(b[0]), "r"(b[1]));
}

__device__ __forceinline__ void cp16(uint32_t saddr, const void* gptr)
{
    asm volatile("cp.async.cg.shared.global [%0], [%1], 16;" :: "r"(saddr), "l"(gptr));
}

__global__ void __launch_bounds__(256, 2) gemm_bf16(
    const __nv_bfloat16* __restrict__ A, const __nv_bfloat16* __restrict__ B,
    float* __restrict__ C, int N)
{
    __shared__ __nv_bfloat16 As[2][TILE_ELEMS];
    __shared__ __nv_bfloat16 Bs[2][TILE_ELEMS];

    const int tid  = threadIdx.x;
    const int lane = tid & 31;
    const int warp = tid >> 5;
    const int wr = warp >> 2;            // 0..1  -> m offset wr*64
    const int wc = warp & 3;             // 0..3  -> n offset wc*32
    const int mBase = blockIdx.y * 128;
    const int nBase = blockIdx.x * 128;

    const uint32_t sA = (uint32_t)__cvta_generic_to_shared(&As[0][0]);
    const uint32_t sB = (uint32_t)__cvta_generic_to_shared(&Bs[0][0]);

    // cp.async mapping: thread t loads A rows {t>>2, 64+t>>2} seg t&3; same for B
    const int lrow = tid >> 2;
    const int lseg = tid & 3;
    const uint32_t swz0 = (uint32_t)(lrow * 32 + ((lseg ^ ((lrow >> 1) & 3)) * 8)) * 2;
    const uint32_t swz1 = (uint32_t)((lrow + 64) * 32 + ((lseg ^ (((lrow + 64) >> 1) & 3)) * 8)) * 2;
    const __nv_bfloat16* gA0 = A + (size_t)(mBase + lrow)      * KEXT + lseg * 8;
    const __nv_bfloat16* gA1 = A + (size_t)(mBase + lrow + 64) * KEXT + lseg * 8;
    const __nv_bfloat16* gB0 = B + (size_t)(nBase + lrow)      * KEXT + lseg * 8;
    const __nv_bfloat16* gB1 = B + (size_t)(nBase + lrow + 64) * KEXT + lseg * 8;

    // ldmatrix addresses (element offsets computed per atom below)
    // A: lane -> row r = wr*64 + a*16 + (lane&15), seg = kk*2 + ((lane>>4)&1)
    const int arow = wr * 64 + (lane & 15);
    const int aseg = (lane >> 4) & 1;
    // B: lane -> row n = wc*32 + p*16 + (lane&7) + ((lane>>4)&1)*8, seg = kk*2 + ((lane>>3)&1)
    const int brow = wc * 32 + (lane & 7) + (((lane >> 4) & 1) << 3);
    const int bseg = (lane >> 3) & 1;

    float acc[4][4][4];
#pragma unroll
    for (int a = 0; a < 4; a++)
#pragma unroll
        for (int n = 0; n < 4; n++)
#pragma unroll
            for (int i = 0; i < 4; i++) acc[a][n][i] = 0.f;

    const int NTILES = KEXT / 32;   // 96

    // prologue: stage 0
    {
        cp16(sA + swz0, gA0); cp16(sA + swz1, gA1);
        cp16(sB + swz0, gB0); cp16(sB + swz1, gB1);
        asm volatile("cp.async.commit_group;");
    }

    for (int t = 0; t < NTILES; t++) {
        // prefetch stage t+1
        if (t + 1 < NTILES) {
            const int k0 = (t + 1) * 32;
            const uint32_t so = ((t + 1) & 1) * (TILE_ELEMS * 2);
            cp16(sA + so + swz0, gA0 + k0); cp16(sA + so + swz1, gA1 + k0);
            cp16(sB + so + swz0, gB0 + k0); cp16(sB + so + swz1, gB1 + k0);
            asm volatile("cp.async.commit_group;");
            asm volatile("cp.async.wait_group 1;");
        } else {
            asm volatile("cp.async.wait_group 0;");
        }
        __syncthreads();

        const uint32_t aBase = sA + (t & 1) * (TILE_ELEMS * 2);
        const uint32_t bBase = sB + (t & 1) * (TILE_ELEMS * 2);

#pragma unroll
        for (int kk = 0; kk < 2; kk++) {
            uint32_t af[4][4];
#pragma unroll
            for (int a = 0; a < 4; a++) {
                int r = arow + a * 16;
                int seg = (kk * 2 + aseg) ^ ((r >> 1) & 3);
                ldm_x4(af[a][0], af[a][1], af[a][2], af[a][3],
                       aBase + (uint32_t)(r * 32 + seg * 8) * 2);
            }
            uint32_t bf[4][2];
#pragma unroll
            for (int p = 0; p < 2; p++) {
                int n = brow + p * 16;
                int seg = (kk * 2 + bseg) ^ ((n >> 1) & 3);
                uint32_t r0, r1, r2, r3;
                ldm_x4(r0, r1, r2, r3, bBase + (uint32_t)(n * 32 + seg * 8) * 2);
                bf[p * 2 + 0][0] = r0; bf[p * 2 + 0][1] = r1;
                bf[p * 2 + 1][0] = r2; bf[p * 2 + 1][1] = r3;
            }
#pragma unroll
            for (int a = 0; a < 4; a++)
#pragma unroll
                for (int n = 0; n < 4; n++)
                    mma16816(acc[a][n], af[a], bf[n]);
        }
        __syncthreads();
    }

    // epilogue
#pragma unroll
    for (int a = 0; a < 4; a++) {
        int row0 = mBase + wr * 64 + a * 16 + (lane >> 2);
#pragma unroll
        for (int n = 0; n < 4; n++) {
            int col = nBase + wc * 32 + n * 8 + (lane & 3) * 2;
            *(float2*)&C[(size_t)row0 * N + col]       = make_float2(acc[a][n][0], acc[a][n][1]);
            *(float2*)&C[(size_t)(row0 + 8) * N + col] = make_float2(acc[a][n][2], acc[a][n][3]);
        }
    }
}

// ---------------------------------------------------------------------------
// Register-tiled causal flash attention (unchanged from R1).
// ---------------------------------------------------------------------------
#define AQT 64
#define AKT 64

__global__ void __launch_bounds__(128, 3) attn_kernel(
    const float* __restrict__ qkv, float* __restrict__ att)
{
    extern __shared__ float sm[];
    float* Qs = sm;           // [64][64]
    float* Ks = sm + 4096;    // [64][64] swizzled
    float* Vs = sm + 8192;    // [64][64]
    float* Ss = sm + 12288;   // [64][64]

    const int b  = blockIdx.z;
    const int h  = blockIdx.y;
    const int qt = (int)(gridDim.x - 1 - blockIdx.x);
    const int tid = threadIdx.x;
    const int tx = tid & 15;
    const int ty = tid >> 4;
    const int q0 = qt * AQT;
    const float scale = 0.125f;

    for (int e = tid; e < 64 * 16; e += 128) {
        int r = e >> 4, c4 = (e & 15) << 2;
        float4 v = *(const float4*)(qkv + ((size_t)(b * SEQ + q0 + r)) * QKV_N + h * DK + c4);
        v.x *= scale; v.y *= scale; v.z *= scale; v.w *= scale;
        *(float4*)&Qs[r * 64 + c4] = v;
    }

    float O[8][4];
    float m[8], l[8];
#pragma unroll
    for (int i = 0; i < 8; i++) {
        m[i] = -1e30f; l[i] = 0.f;
        O[i][0] = O[i][1] = O[i][2] = O[i][3] = 0.f;
    }
    __syncthreads();

    for (int kt = 0; kt <= qt; kt++) {
        const int kbase = kt * AKT;

        for (int e = tid; e < 64 * 16; e += 128) {
            int r = e >> 4, c4 = e & 15;
            size_t gbase = ((size_t)(b * SEQ + kbase + r)) * QKV_N + h * DK + (c4 << 2);
            float4 kv = *(const float4*)(qkv + gbase + DMODEL);
            *(float4*)&Ks[r * 64 + ((c4 ^ (r >> 2)) << 2)] = kv;
            float4 vv = *(const float4*)(qkv + gbase + 2 * DMODEL);
            *(float4*)&Vs[r * 64 + (c4 << 2)] = vv;
        }
        __syncthreads();

        float s[8][4];
#pragma unroll
        for (int i = 0; i < 8; i++) { s[i][0]=0.f; s[i][1]=0.f; s[i][2]=0.f; s[i][3]=0.f; }

#pragma unroll 4
        for (int kk4 = 0; kk4 < 16; kk4++) {
            const int kcol = ((kk4 ^ tx) << 2);
            float4 kv0 = *(const float4*)&Ks[(tx * 4 + 0) * 64 + kcol];
            float4 kv1 = *(const float4*)&Ks[(tx * 4 + 1) * 64 + kcol];
            float4 kv2 = *(const float4*)&Ks[(tx * 4 + 2) * 64 + kcol];
            float4 kv3 = *(const float4*)&Ks[(tx * 4 + 3) * 64 + kcol];
#pragma unroll
            for (int i = 0; i < 8; i++) {
                float4 qv = *(const float4*)&Qs[(ty * 8 + i) * 64 + (kk4 << 2)];
                s[i][0] = fmaf(qv.x, kv0.x, fmaf(qv.y, kv0.y, fmaf(qv.z, kv0.z, fmaf(qv.w, kv0.w, s[i][0]))));
                s[i][1] = fmaf(qv.x, kv1.x, fmaf(qv.y, kv1.y, fmaf(qv.z, kv1.z, fmaf(qv.w, kv1.w, s[i][1]))));
                s[i][2] = fmaf(qv.x, kv2.x, fmaf(qv.y, kv2.y, fmaf(qv.z, kv2.z, fmaf(qv.w, kv2.w, s[i][2]))));
                s[i][3] = fmaf(qv.x, kv3.x, fmaf(qv.y, kv3.y, fmaf(qv.z, kv3.z, fmaf(qv.w, kv3.w, s[i][3]))));
            }
        }

        if (kt == qt) {
#pragma unroll
            for (int i = 0; i < 8; i++) {
                int qq = ty * 8 + i;
#pragma unroll
                for (int j = 0; j < 4; j++)
                    if (tx * 4 + j > qq) s[i][j] = -1e30f;
            }
        }

#pragma unroll
        for (int i = 0; i < 8; i++) {
            float mx = fmaxf(fmaxf(s[i][0], s[i][1]), fmaxf(s[i][2], s[i][3]));
            mx = fmaxf(mx, __shfl_xor_sync(0xffffffffu, mx, 1));
            mx = fmaxf(mx, __shfl_xor_sync(0xffffffffu, mx, 2));
            mx = fmaxf(mx, __shfl_xor_sync(0xffffffffu, mx, 4));
            mx = fmaxf(mx, __shfl_xor_sync(0xffffffffu, mx, 8));
            float mn = fmaxf(m[i], mx);
            float p0 = __expf(s[i][0] - mn);
            float p1 = __expf(s[i][1] - mn);
            float p2 = __expf(s[i][2] - mn);
            float p3 = __expf(s[i][3] - mn);
            float sum = (p0 + p1) + (p2 + p3);
            sum += __shfl_xor_sync(0xffffffffu, sum, 1);
            sum += __shfl_xor_sync(0xffffffffu, sum, 2);
            sum += __shfl_xor_sync(0xffffffffu, sum, 4);
            sum += __shfl_xor_sync(0xffffffffu, sum, 8);
            float corr = __expf(m[i] - mn);
            m[i] = mn;
            l[i] = l[i] * corr + sum;
            O[i][0] *= corr; O[i][1] *= corr; O[i][2] *= corr; O[i][3] *= corr;
            *(float4*)&Ss[(ty * 8 + i) * 64 + tx * 4] = make_float4(p0, p1, p2, p3);
        }
        __syncthreads();

#pragma unroll 4
        for (int j4 = 0; j4 < 16; j4++) {
            float4 v0 = *(const float4*)&Vs[(j4 * 4 + 0) * 64 + tx * 4];
            float4 v1 = *(const float4*)&Vs[(j4 * 4 + 1) * 64 + tx * 4];
            float4 v2 = *(const float4*)&Vs[(j4 * 4 + 2) * 64 + tx * 4];
            float4 v3 = *(const float4*)&Vs[(j4 * 4 + 3) * 64 + tx * 4];
#pragma unroll
            for (int i = 0; i < 8; i++) {
                float4 p = *(const float4*)&Ss[(ty * 8 + i) * 64 + j4 * 4];
                O[i][0] = fmaf(p.x, v0.x, fmaf(p.y, v1.x, fmaf(p.z, v2.x, fmaf(p.w, v3.x, O[i][0]))));
                O[i][1] = fmaf(p.x, v0.y, fmaf(p.y, v1.y, fmaf(p.z, v2.y, fmaf(p.w, v3.y, O[i][1]))));
                O[i][2] = fmaf(p.x, v0.z, fmaf(p.y, v1.z, fmaf(p.z, v2.z, fmaf(p.w, v3.z, O[i][2]))));
                O[i][3] = fmaf(p.x, v0.w, fmaf(p.y, v1.w, fmaf(p.z, v2.w, fmaf(p.w, v3.w, O[i][3]))));
            }
        }
        __syncthreads();
    }

#pragma unroll
    for (int i = 0; i < 8; i++) {
        float inv = 1.f / l[i];
        float* orow = att + ((size_t)(b * SEQ + q0 + ty * 8 + i)) * DMODEL + h * DK;
        *(float4*)(orow + tx * 4) = make_float4(O[i][0] * inv, O[i][1] * inv,
                                                O[i][2] * inv, O[i][3] * inv);
    }
}

// ---------------------------------------------------------------------------
// kernel_launch
// ---------------------------------------------------------------------------
extern "C" void kernel_launch(void* const* d_in, const int* in_sizes, int n_in,
                              void* d_out, int out_size)
{
    const float* x     = (const float*)d_in[0];   // [2, 2048, 1024]
    const float* W_qkv = (const float*)d_in[1];   // [3072, 1024]
    const float* W_out = (const float*)d_in[2];   // [1024, 1024]
    float* out = (float*)d_out;                   // [2, 2048, 1024]

    float* qkv_ptr = nullptr;  float* att_ptr = nullptr;
    __nv_bfloat16 *xe, *wqkve, *wute, *atte;
    cudaGetSymbolAddress((void**)&qkv_ptr, g_qkv);
    cudaGetSymbolAddress((void**)&att_ptr, g_att);
    cudaGetSymbolAddress((void**)&xe,    g_xe);
    cudaGetSymbolAddress((void**)&wqkve, g_wqkve);
    cudaGetSymbolAddress((void**)&wute,  g_wute);
    cudaGetSymbolAddress((void**)&atte,  g_atte);

    cudaFuncSetAttribute(attn_kernel, cudaFuncAttributeMaxDynamicSharedMemorySize, 65536);

    // 0) split conversions (inputs)
    {
        size_t tx_ = (size_t)MTOT * DMODEL;
        conv_split<1><<<(unsigned)((tx_/4 + 255)/256), 256>>>(x, xe, DMODEL, tx_);
        size_t tw = (size_t)QKV_N * DMODEL;
        conv_split<0><<<(unsigned)((tw/4 + 255)/256), 256>>>(W_qkv, wqkve, DMODEL, tw);
        size_t tu = (size_t)DMODEL * DMODEL;
        conv_split<0><<<(unsigned)((tu/4 + 255)/256), 256>>>(W_out, wute, DMODEL, tu);
    }
    // 1) QKV projection (tensor core, bf16-split): [4096,3072]
    {
        dim3 grid(QKV_N / 128, MTOT / 128);
        gemm_bf16<<<grid, 256>>>(xe, wqkve, qkv_ptr, QKV_N);
    }
    // 2) causal flash attention -> g_att
    {
        dim3 grid(SEQ / AQT, NHEADS, BATCH);
        attn_kernel<<<grid, 128, 65536>>>(qkv_ptr, att_ptr);
    }
    // 3) convert attention output, then output projection -> d_out
    {
        size_t ta = (size_t)MTOT * DMODEL;
        conv_split<1><<<(unsigned)((ta/4 + 255)/256), 256>>>(att_ptr, atte, DMODEL, ta);
        dim3 grid(DMODEL / 128, MTOT / 128);
        gemm_bf16<<<grid, 256>>>(atte, wute, out, DMODEL);
    }
}

// round 4
// speedup vs baseline: 2.8651x; 1.4372x over previous
#include <cuda_runtime.h>
#include <cuda_bf16.h>
#include <math.h>
#include <stdint.h>

// Problem constants
#define BATCH 2
#define SEQ   2048
#define DMODEL 1024
#define NHEADS 16
#define DK    64
#define MTOT  (BATCH*SEQ)          // 4096
#define QKV_N (3*DMODEL)           // 3072
#define KEXT  (3*DMODEL)           // 3072 extended-K for bf16 split

// Scratch (device globals — no allocation allowed)
__device__ float g_qkv[(size_t)MTOT * QKV_N];             // f32 qkv
__device__ __nv_bfloat16 g_xe   [(size_t)MTOT  * KEXT];   // x extended   (A: hi,lo,hi)
__device__ __nv_bfloat16 g_wqkve[(size_t)QKV_N * KEXT];   // W_qkv ext    (B: hi,hi,lo)
__device__ __nv_bfloat16 g_wute [(size_t)DMODEL* KEXT];   // W_out ext    (B)
__device__ __nv_bfloat16 g_atte [(size_t)MTOT  * KEXT];   // attention out ext (A)

// ---------------------------------------------------------------------------
// helpers
// ---------------------------------------------------------------------------
__device__ __forceinline__ void pack_hilo(float a, float b, uint32_t& hi, uint32_t& lo)
{
    __nv_bfloat16 ha = __float2bfloat16_rn(a), hb = __float2bfloat16_rn(b);
    __nv_bfloat162 h; h.x = ha; h.y = hb;
    __nv_bfloat162 l;
    l.x = __float2bfloat16_rn(a - __bfloat162float(ha));
    l.y = __float2bfloat16_rn(b - __bfloat162float(hb));
    hi = *(uint32_t*)&h; lo = *(uint32_t*)&l;
}

__device__ __forceinline__ void ldm_x4(uint32_t& r0, uint32_t& r1, uint32_t& r2, uint32_t& r3,
                                       uint32_t addr)
{
    asm volatile("ldmatrix.sync.aligned.m8n8.x4.shared.b16 {%0,%1,%2,%3}, [%4];"
                 : "=r"(r0), "=r"(r1), "=r"(r2), "=r"(r3) : "r"(addr));
}

__device__ __forceinline__ void ldm_x4_t(uint32_t& r0, uint32_t& r1, uint32_t& r2, uint32_t& r3,
                                         uint32_t addr)
{
    asm volatile("ldmatrix.sync.aligned.m8n8.x4.trans.shared.b16 {%0,%1,%2,%3}, [%4];"
                 : "=r"(r0), "=r"(r1), "=r"(r2), "=r"(r3) : "r"(addr));
}

__device__ __forceinline__ void mma16816(float* d, const uint32_t* a, const uint32_t* b)
{
    asm volatile(
        "mma.sync.aligned.m16n8k16.row.col.f32.bf16.bf16.f32 "
        "{%0,%1,%2,%3}, {%4,%5,%6,%7}, {%8,%9}, {%0,%1,%2,%3};"
        : "+f"(d[0]), "+f"(d[1]), "+f"(d[2]), "+f"(d[3])
        : "r"(a[0]), "r"(a[1]), "r"(a[2]), "r"(a[3]), "r"(b[0]), "r"(b[1]));
}

__device__ __forceinline__ void cp16(uint32_t saddr, const void* gptr)
{
    asm volatile("cp.async.cg.shared.global [%0], [%1], 16;" :: "r"(saddr), "l"(gptr));
}

// convert 8 f32 -> hi/lo bf16 16B stores
__device__ __forceinline__ void cvt_store8(__nv_bfloat16* dhi, __nv_bfloat16* dlo,
                                           float4 f0, float4 f1)
{
    uint32_t h0,h1,h2,h3,l0,l1,l2,l3;
    pack_hilo(f0.x, f0.y, h0, l0);
    pack_hilo(f0.z, f0.w, h1, l1);
    pack_hilo(f1.x, f1.y, h2, l2);
    pack_hilo(f1.z, f1.w, h3, l3);
    *(uint4*)dhi = make_uint4(h0, h1, h2, h3);
    *(uint4*)dlo = make_uint4(l0, l1, l2, l3);
}

// ---------------------------------------------------------------------------
// Split-conversion kernels: f32 [R,K] -> bf16 [R,3K]
//  A mode: [k]=hi  [K+k]=lo  [2K+k]=hi ;  B mode: [k]=hi [K+k]=hi [2K+k]=lo
// ---------------------------------------------------------------------------
template<int ISA>
__global__ void conv_split(const float* __restrict__ in, __nv_bfloat16* __restrict__ out,
                           int K, size_t total)
{
    size_t idx = ((size_t)blockIdx.x * blockDim.x + threadIdx.x) * 4;
    if (idx >= total) return;
    int r = (int)(idx / K);
    int k = (int)(idx % K);
    float4 v = *(const float4*)(in + idx);
    uint32_t hi01, hi23, lo01, lo23;
    pack_hilo(v.x, v.y, hi01, lo01);
    pack_hilo(v.z, v.w, hi23, lo23);
    __nv_bfloat16* o = out + (size_t)r * (3 * K) + k;
    *(uint32_t*)(o + 0) = hi01;  *(uint32_t*)(o + 2) = hi23;
    if (ISA) {
        *(uint32_t*)(o + K + 0)     = lo01; *(uint32_t*)(o + K + 2)     = lo23;
        *(uint32_t*)(o + 2 * K + 0) = hi01; *(uint32_t*)(o + 2 * K + 2) = hi23;
    } else {
        *(uint32_t*)(o + K + 0)     = hi01; *(uint32_t*)(o + K + 2)     = hi23;
        *(uint32_t*)(o + 2 * K + 0) = lo01; *(uint32_t*)(o + 2 * K + 2) = lo23;
    }
}

// ---------------------------------------------------------------------------
// bf16 tensor-core GEMM: C[M,N] f32 = A[M,KEXT] * B[N,KEXT]^T (from R3, works)
// ---------------------------------------------------------------------------
#define TILE_ELEMS (128*32)

__global__ void __launch_bounds__(256, 2) gemm_bf16(
    const __nv_bfloat16* __restrict__ A, const __nv_bfloat16* __restrict__ B,
    float* __restrict__ C, int N)
{
    __shared__ __nv_bfloat16 As[2][TILE_ELEMS];
    __shared__ __nv_bfloat16 Bs[2][TILE_ELEMS];

    const int tid  = threadIdx.x;
    const int lane = tid & 31;
    const int warp = tid >> 5;
    const int wr = warp >> 2;
    const int wc = warp & 3;
    const int mBase = blockIdx.y * 128;
    const int nBase = blockIdx.x * 128;

    const uint32_t sA = (uint32_t)__cvta_generic_to_shared(&As[0][0]);
    const uint32_t sB = (uint32_t)__cvta_generic_to_shared(&Bs[0][0]);

    const int lrow = tid >> 2;
    const int lseg = tid & 3;
    const uint32_t swz0 = (uint32_t)(lrow * 32 + ((lseg ^ ((lrow >> 1) & 3)) * 8)) * 2;
    const uint32_t swz1 = (uint32_t)((lrow + 64) * 32 + ((lseg ^ (((lrow + 64) >> 1) & 3)) * 8)) * 2;
    const __nv_bfloat16* gA0 = A + (size_t)(mBase + lrow)      * KEXT + lseg * 8;
    const __nv_bfloat16* gA1 = A + (size_t)(mBase + lrow + 64) * KEXT + lseg * 8;
    const __nv_bfloat16* gB0 = B + (size_t)(nBase + lrow)      * KEXT + lseg * 8;
    const __nv_bfloat16* gB1 = B + (size_t)(nBase + lrow + 64) * KEXT + lseg * 8;

    const int arow = wr * 64 + (lane & 15);
    const int aseg = (lane >> 4) & 1;
    const int brow = wc * 32 + (lane & 7) + (((lane >> 4) & 1) << 3);
    const int bseg = (lane >> 3) & 1;

    float acc[4][4][4];
#pragma unroll
    for (int a = 0; a < 4; a++)
#pragma unroll
        for (int n = 0; n < 4; n++)
#pragma unroll
            for (int i = 0; i < 4; i++) acc[a][n][i] = 0.f;

    const int NTILES = KEXT / 32;

    cp16(sA + swz0, gA0); cp16(sA + swz1, gA1);
    cp16(sB + swz0, gB0); cp16(sB + swz1, gB1);
    asm volatile("cp.async.commit_group;");

    for (int t = 0; t < NTILES; t++) {
        if (t + 1 < NTILES) {
            const int k0 = (t + 1) * 32;
            const uint32_t so = ((t + 1) & 1) * (TILE_ELEMS * 2);
            cp16(sA + so + swz0, gA0 + k0); cp16(sA + so + swz1, gA1 + k0);
            cp16(sB + so + swz0, gB0 + k0); cp16(sB + so + swz1, gB1 + k0);
            asm volatile("cp.async.commit_group;");
            asm volatile("cp.async.wait_group 1;");
        } else {
            asm volatile("cp.async.wait_group 0;");
        }
        __syncthreads();

        const uint32_t aBase = sA + (t & 1) * (TILE_ELEMS * 2);
        const uint32_t bBase = sB + (t & 1) * (TILE_ELEMS * 2);

#pragma unroll
        for (int kk = 0; kk < 2; kk++) {
            uint32_t af[4][4];
#pragma unroll
            for (int a = 0; a < 4; a++) {
                int r = arow + a * 16;
                int seg = (kk * 2 + aseg) ^ ((r >> 1) & 3);
                ldm_x4(af[a][0], af[a][1], af[a][2], af[a][3],
                       aBase + (uint32_t)(r * 32 + seg * 8) * 2);
            }
            uint32_t bf[4][2];
#pragma unroll
            for (int p = 0; p < 2; p++) {
                int n = brow + p * 16;
                int seg = (kk * 2 + bseg) ^ ((n >> 1) & 3);
                uint32_t r0, r1, r2, r3;
                ldm_x4(r0, r1, r2, r3, bBase + (uint32_t)(n * 32 + seg * 8) * 2);
                bf[p * 2 + 0][0] = r0; bf[p * 2 + 0][1] = r1;
                bf[p * 2 + 1][0] = r2; bf[p * 2 + 1][1] = r3;
            }
#pragma unroll
            for (int a = 0; a < 4; a++)
#pragma unroll
                for (int n = 0; n < 4; n++)
                    mma16816(acc[a][n], af[a], bf[n]);
        }
        __syncthreads();
    }

#pragma unroll
    for (int a = 0; a < 4; a++) {
        int row0 = mBase + wr * 64 + a * 16 + (lane >> 2);
#pragma unroll
        for (int n = 0; n < 4; n++) {
            int col = nBase + wc * 32 + n * 8 + (lane & 3) * 2;
            *(float2*)&C[(size_t)row0 * N + col]       = make_float2(acc[a][n][0], acc[a][n][1]);
            *(float2*)&C[(size_t)(row0 + 8) * N + col] = make_float2(acc[a][n][2], acc[a][n][3]);
        }
    }
}

// ---------------------------------------------------------------------------
// Tensor-core causal flash attention with bf16 hi/lo split (fp32-accurate).
// Block: 256 thr / 8 warps. Q tile = 128 rows; warp w owns rows 16w..16w+15.
// K tiles of 64 keys. Smem (32KB dynamic):
//   phase Q:  Qhi[128][64] @0, Qlo @16KB
//   per tile: Khi[64][64] @0, Klo @8KB, Vhi @16KB, Vlo @24KB  (bf16, XOR swizzle)
// Epilogue writes bf16 split A-layout directly to g_atte (hi|lo|hi).
// ---------------------------------------------------------------------------
__global__ void __launch_bounds__(256, 1) attn_tc(
    const float* __restrict__ qkv, __nv_bfloat16* __restrict__ atte)
{
    extern __shared__ __nv_bfloat16 sm[];
    const uint32_t sbase = (uint32_t)__cvta_generic_to_shared(sm);

    const int b = blockIdx.z, h = blockIdx.y;
    const int qt = (int)(gridDim.x - 1 - blockIdx.x);   // heavy tiles first
    const int q0 = qt * 128;
    const int tid = threadIdx.x;
    const int lane = tid & 31, warp = tid >> 5;

    // --- Stage Q (pre-scaled by 1/8), convert to hi/lo, swizzled smem
    for (int e = tid; e < 1024; e += 256) {            // 128 rows x 8 segs
        int r = e >> 3, sg = e & 7;
        const float* gq = qkv + ((size_t)(b * SEQ + q0 + r)) * QKV_N + h * DK + sg * 8;
        float4 f0 = *(const float4*)gq;
        float4 f1 = *(const float4*)(gq + 4);
        f0.x *= 0.125f; f0.y *= 0.125f; f0.z *= 0.125f; f0.w *= 0.125f;
        f1.x *= 0.125f; f1.y *= 0.125f; f1.z *= 0.125f; f1.w *= 0.125f;
        int off = r * 64 + ((sg ^ (r & 7)) * 8);
        cvt_store8(sm + off, sm + 8192 + off, f0, f1);
    }
    __syncthreads();

    // --- Q fragments into registers (4 k-steps x 4 regs, hi+lo)
    uint32_t qh[4][4], ql[4][4];
    {
        const int r = warp * 16 + (lane & 15);
        const int sgx = lane >> 4;
#pragma unroll
        for (int ks = 0; ks < 4; ks++) {
            int sg = (2 * ks + sgx) ^ (r & 7);
            uint32_t ad = sbase + (uint32_t)(r * 64 + sg * 8) * 2;
            ldm_x4(qh[ks][0], qh[ks][1], qh[ks][2], qh[ks][3], ad);
            ldm_x4(ql[ks][0], ql[ks][1], ql[ks][2], ql[ks][3], ad + 16384);
        }
    }

    float o[8][4];
#pragma unroll
    for (int t = 0; t < 8; t++) { o[t][0]=0.f; o[t][1]=0.f; o[t][2]=0.f; o[t][3]=0.f; }
    float m0 = -1e30f, m1 = -1e30f, l0 = 0.f, l1 = 0.f;

    const int ktmax = q0 / 64 + 1;
    for (int kt = 0; kt <= ktmax; kt++) {
        const int kbase = kt * 64;
        __syncthreads();   // everyone done reading previous tile / Q stage
        // load + convert K,V tile
        for (int e = tid; e < 512; e += 256) {          // 64 rows x 8 segs
            int r = e >> 3, sg = e & 7;
            size_t g = ((size_t)(b * SEQ + kbase + r)) * QKV_N + h * DK + sg * 8;
            int off = r * 64 + ((sg ^ (r & 7)) * 8);
            float4 k0 = *(const float4*)(qkv + g + DMODEL);
            float4 k1 = *(const float4*)(qkv + g + DMODEL + 4);
            cvt_store8(sm + off,        sm + 4096 + off,  k0, k1);
            float4 v0 = *(const float4*)(qkv + g + 2 * DMODEL);
            float4 v1 = *(const float4*)(qkv + g + 2 * DMODEL + 4);
            cvt_store8(sm + 8192 + off, sm + 12288 + off, v0, v1);
        }
        __syncthreads();

        if (kbase <= q0 + warp * 16 + 15) {   // skip fully-masked warps
            // ---- S = Q K^T (3-term split), accumulators in mma layout
            float s[8][4];
#pragma unroll
            for (int t = 0; t < 8; t++) { s[t][0]=0.f; s[t][1]=0.f; s[t][2]=0.f; s[t][3]=0.f; }

#pragma unroll
            for (int kk = 0; kk < 4; kk++) {
#pragma unroll
                for (int np = 0; np < 4; np++) {
                    int krow = np * 16 + (lane & 7) + (((lane >> 4) & 1) << 3);
                    int ksg = (2 * kk + ((lane >> 3) & 1)) ^ (krow & 7);
                    uint32_t ad = sbase + (uint32_t)(krow * 64 + ksg * 8) * 2;
                    uint32_t bh0, bh1, bh2, bh3, bl0, bl1, bl2, bl3;
                    ldm_x4(bh0, bh1, bh2, bh3, ad);
                    ldm_x4(bl0, bl1, bl2, bl3, ad + 8192);
                    uint32_t bb[2];
                    bb[0] = bh0; bb[1] = bh1;
                    mma16816(s[2*np],   qh[kk], bb);
                    mma16816(s[2*np],   ql[kk], bb);
                    bb[0] = bh2; bb[1] = bh3;
                    mma16816(s[2*np+1], qh[kk], bb);
                    mma16816(s[2*np+1], ql[kk], bb);
                    bb[0] = bl0; bb[1] = bl1;
                    mma16816(s[2*np],   qh[kk], bb);
                    bb[0] = bl2; bb[1] = bl3;
                    mma16816(s[2*np+1], qh[kk], bb);
                }
            }

            // ---- causal mask (only near diagonal)
            const int rg0 = q0 + warp * 16 + (lane >> 2);
            if (kbase + 63 > q0 + warp * 16) {
#pragma unroll
                for (int nt = 0; nt < 8; nt++) {
                    int c0 = kbase + nt * 8 + 2 * (lane & 3);
                    if (c0     > rg0)     s[nt][0] = -1e30f;
                    if (c0 + 1 > rg0)     s[nt][1] = -1e30f;
                    if (c0     > rg0 + 8) s[nt][2] = -1e30f;
                    if (c0 + 1 > rg0 + 8) s[nt][3] = -1e30f;
                }
            }

            // ---- online softmax (rows rg0, rg0+8)
            float mx0 = -1e30f, mx1 = -1e30f;
#pragma unroll
            for (int nt = 0; nt < 8; nt++) {
                mx0 = fmaxf(mx0, fmaxf(s[nt][0], s[nt][1]));
                mx1 = fmaxf(mx1, fmaxf(s[nt][2], s[nt][3]));
            }
            mx0 = fmaxf(mx0, __shfl_xor_sync(0xffffffffu, mx0, 1));
            mx0 = fmaxf(mx0, __shfl_xor_sync(0xffffffffu, mx0, 2));
            mx1 = fmaxf(mx1, __shfl_xor_sync(0xffffffffu, mx1, 1));
            mx1 = fmaxf(mx1, __shfl_xor_sync(0xffffffffu, mx1, 2));
            float mn0 = fmaxf(m0, mx0), mn1 = fmaxf(m1, mx1);
            float cr0 = __expf(m0 - mn0), cr1 = __expf(m1 - mn1);
            m0 = mn0; m1 = mn1;
            float sum0 = 0.f, sum1 = 0.f;
#pragma unroll
            for (int nt = 0; nt < 8; nt++) {
                s[nt][0] = __expf(s[nt][0] - mn0);
                s[nt][1] = __expf(s[nt][1] - mn0);
                s[nt][2] = __expf(s[nt][2] - mn1);
                s[nt][3] = __expf(s[nt][3] - mn1);
                sum0 += s[nt][0] + s[nt][1];
                sum1 += s[nt][2] + s[nt][3];
            }
            sum0 += __shfl_xor_sync(0xffffffffu, sum0, 1);
            sum0 += __shfl_xor_sync(0xffffffffu, sum0, 2);
            sum1 += __shfl_xor_sync(0xffffffffu, sum1, 1);
            sum1 += __shfl_xor_sync(0xffffffffu, sum1, 2);
            l0 = l0 * cr0 + sum0;
            l1 = l1 * cr1 + sum1;
#pragma unroll
            for (int t = 0; t < 8; t++) {
                o[t][0] *= cr0; o[t][1] *= cr0; o[t][2] *= cr1; o[t][3] *= cr1;
            }

            // ---- O += P V (3-term split); P fragments straight from accumulators
#pragma unroll
            for (int ks = 0; ks < 4; ks++) {
                uint32_t ah[4], al[4];
                pack_hilo(s[2*ks][0],   s[2*ks][1],   ah[0], al[0]);
                pack_hilo(s[2*ks][2],   s[2*ks][3],   ah[1], al[1]);
                pack_hilo(s[2*ks+1][0], s[2*ks+1][1], ah[2], al[2]);
                pack_hilo(s[2*ks+1][2], s[2*ks+1][3], ah[3], al[3]);
#pragma unroll
                for (int cp = 0; cp < 4; cp++) {
                    int vrow = ks * 16 + (lane & 15);
                    int vsg = (2 * cp + (lane >> 4)) ^ (vrow & 7);
                    uint32_t va = sbase + 16384 + (uint32_t)(vrow * 64 + vsg * 8) * 2;
                    uint32_t vh0, vh1, vh2, vh3, vl0, vl1, vl2, vl3;
                    ldm_x4_t(vh0, vh1, vh2, vh3, va);
                    ldm_x4_t(vl0, vl1, vl2, vl3, va + 8192);
                    uint32_t bb[2];
                    bb[0] = vh0; bb[1] = vh1;
                    mma16816(o[2*cp],   ah, bb);
                    mma16816(o[2*cp],   al, bb);
                    bb[0] = vl0; bb[1] = vl1;
                    mma16816(o[2*cp],   ah, bb);
                    bb[0] = vh2; bb[1] = vh3;
                    mma16816(o[2*cp+1], ah, bb);
                    mma16816(o[2*cp+1], al, bb);
                    bb[0] = vl2; bb[1] = vl3;
                    mma16816(o[2*cp+1], ah, bb);
                }
            }
        }
    }

    // ---- epilogue: normalize, write split-bf16 extended layout (hi|lo|hi)
    const float inv0 = 1.f / l0, inv1 = 1.f / l1;
    const int rg0 = q0 + warp * 16 + (lane >> 2);
    const size_t ro0 = (size_t)(b * SEQ + rg0) * KEXT;
    const size_t ro1 = (size_t)(b * SEQ + rg0 + 8) * KEXT;
#pragma unroll
    for (int nt = 0; nt < 8; nt++) {
        int col = h * DK + nt * 8 + 2 * (lane & 3);
        uint32_t hi, lo;
        pack_hilo(o[nt][0] * inv0, o[nt][1] * inv0, hi, lo);
        *(uint32_t*)(atte + ro0 + col)          = hi;
        *(uint32_t*)(atte + ro0 + DMODEL + col) = lo;
        *(uint32_t*)(atte + ro0 + 2*DMODEL + col) = hi;
        pack_hilo(o[nt][2] * inv1, o[nt][3] * inv1, hi, lo);
        *(uint32_t*)(atte + ro1 + col)          = hi;
        *(uint32_t*)(atte + ro1 + DMODEL + col) = lo;
        *(uint32_t*)(atte + ro1 + 2*DMODEL + col) = hi;
    }
}

// ---------------------------------------------------------------------------
// kernel_launch
// ---------------------------------------------------------------------------
extern "C" void kernel_launch(void* const* d_in, const int* in_sizes, int n_in,
                              void* d_out, int out_size)
{
    const float* x     = (const float*)d_in[0];   // [2, 2048, 1024]
    const float* W_qkv = (const float*)d_in[1];   // [3072, 1024]
    const float* W_out = (const float*)d_in[2];   // [1024, 1024]
    float* out = (float*)d_out;                   // [2, 2048, 1024]

    float* qkv_ptr = nullptr;
    __nv_bfloat16 *xe, *wqkve, *wute, *atte;
    cudaGetSymbolAddress((void**)&qkv_ptr, g_qkv);
    cudaGetSymbolAddress((void**)&xe,    g_xe);
    cudaGetSymbolAddress((void**)&wqkve, g_wqkve);
    cudaGetSymbolAddress((void**)&wute,  g_wute);
    cudaGetSymbolAddress((void**)&atte,  g_atte);

    // 0) split conversions (inputs)
    {
        size_t tx_ = (size_t)MTOT * DMODEL;
        conv_split<1><<<(unsigned)((tx_/4 + 255)/256), 256>>>(x, xe, DMODEL, tx_);
        size_t tw = (size_t)QKV_N * DMODEL;
        conv_split<0><<<(unsigned)((tw/4 + 255)/256), 256>>>(W_qkv, wqkve, DMODEL, tw);
        size_t tu = (size_t)DMODEL * DMODEL;
        conv_split<0><<<(unsigned)((tu/4 + 255)/256), 256>>>(W_out, wute, DMODEL, tu);
    }
    // 1) QKV projection (tensor core, bf16-split): [4096,3072] f32
    {
        dim3 grid(QKV_N / 128, MTOT / 128);
        gemm_bf16<<<grid, 256>>>(xe, wqkve, qkv_ptr, QKV_N);
    }
    // 2) tensor-core causal flash attention -> g_atte (bf16 split layout)
    {
        dim3 grid(SEQ / 128, NHEADS, BATCH);
        attn_tc<<<grid, 256, 32768>>>(qkv_ptr, atte);
    }
    // 3) output projection -> d_out
    {
        dim3 grid(DMODEL / 128, MTOT / 128);
        gemm_bf16<<<grid, 256>>>(atte, wute, out, DMODEL);
    }
}